// round 15
// baseline (speedup 1.0000x reference)
#include <cuda_runtime.h>
#include <cuda_fp16.h>
#include <math.h>
#include <stdint.h>

#define B 2048
#define N 128
#define D 512
#define BD (B * D)
#define NW 4             // warps per CTA in fuse kernel
#define NT (NW * 32)     // 128 threads
#define DEPTH 3          // z-ring depth in row pairs

// Scratch: cw = content @ cow (rows interleaved: 2b=text[b], 2b+1=img[b])
__device__ float g_cw[2 * B * D];

__device__ __forceinline__ float tanha(float x) {
    float y;
    asm("tanh.approx.f32 %0, %1;" : "=f"(y) : "f"(x));
    return y;
}
__device__ __forceinline__ float ex2(float x) {
    float y;
    asm("ex2.approx.f32 %0, %1;" : "=f"(y) : "f"(x));
    return y;
}
__device__ __forceinline__ void cp_async16(void* smem_dst, const void* gmem_src) {
    uint32_t s = (uint32_t)__cvta_generic_to_shared(smem_dst);
    asm volatile("cp.async.ca.shared.global [%0], [%1], 16;" :: "r"(s), "l"(gmem_src));
}
__device__ __forceinline__ void cp_commit() {
    asm volatile("cp.async.commit_group;");
}

// fp16 hi/lo split: x = hi + lo with |lo| <= 2^-11 |x|  (22 effective bits)
__device__ __forceinline__ void f2h_split(float x, uint16_t& hi, uint16_t& lo) {
    __half h = __float2half_rn(x);
    __half l = __float2half_rn(x - __half2float(h));
    hi = __half_as_ushort(h);
    lo = __half_as_ushort(l);
}
__device__ __forceinline__ uint32_t packh2(uint16_t a, uint16_t b) {
    return (uint32_t)a | ((uint32_t)b << 16);
}

// m16n8k16 row.col f32.f16.f16.f32
__device__ __forceinline__ void mma_f16(float c[4], const uint32_t a[4], const uint32_t b[2]) {
    asm volatile(
        "mma.sync.aligned.m16n8k16.row.col.f32.f16.f16.f32 "
        "{%0,%1,%2,%3}, {%4,%5,%6,%7}, {%8,%9}, {%0,%1,%2,%3};"
        : "+f"(c[0]), "+f"(c[1]), "+f"(c[2]), "+f"(c[3])
        : "r"(a[0]), "r"(a[1]), "r"(a[2]), "r"(a[3]), "r"(b[0]), "r"(b[1]));
}

// ---------------------------------------------------------------------------
// Kernel 1: cw[4096,512] = A[4096,512] @ cow[512,512] via fp16x3 mma.sync
// (hi/lo split, 3 terms; lo*lo dropped ~2^-22). UNCHANGED from R13 (passing).
// MMA-throughput-bound at ~41 us on the legacy tensor path (~150 TF/s).
// ---------------------------------------------------------------------------
#define GM_KT 32
#define AST 36     // A row stride (floats): [m][k] padded
#define WST 132    // W row stride (floats): [k][n] padded
#define A_STAGE (64 * AST)
#define W_STAGE (GM_KT * WST)
#define GEMM_SMEM_BYTES ((2 * A_STAGE + 2 * W_STAGE) * 4)

__global__ __launch_bounds__(256) void gemm_cw_f16(
    const float* __restrict__ text,
    const float* __restrict__ img,
    const float* __restrict__ cow)
{
    extern __shared__ float gsm[];
    float* As = gsm;
    float* Ws = gsm + 2 * A_STAGE;

    const int t = threadIdx.x;
    const int wid = t >> 5;
    const int lane = t & 31;
    const int warp_m = (wid & 1) * 32;
    const int warp_n = (wid >> 1) * 32;
    const int brow = blockIdx.y * 64;
    const int bcol = blockIdx.x * 128;
    const int g  = lane >> 2;
    const int tg = lane & 3;

    float c[2][4][4];
#pragma unroll
    for (int mi = 0; mi < 2; mi++)
#pragma unroll
        for (int ni = 0; ni < 4; ni++)
#pragma unroll
            for (int j = 0; j < 4; j++) c[mi][ni][j] = 0.f;

    auto load_stage = [&](int st, int k0) {
#pragma unroll
        for (int s = 0; s < 2; s++) {
            int f = t + 256 * s;
            int r = f >> 3;
            int kk = (f & 7) * 4;
            int gr = brow + r;
            const float* src = ((gr & 1) ? img : text) + (size_t)(gr >> 1) * D + k0 + kk;
            cp_async16(&As[st * A_STAGE + r * AST + kk], src);
        }
#pragma unroll
        for (int s = 0; s < 4; s++) {
            int f = t + 256 * s;
            int kk = f >> 5;
            int n = (f & 31) * 4;
            const float* src = cow + (size_t)(k0 + kk) * D + bcol + n;
            cp_async16(&Ws[st * W_STAGE + kk * WST + n], src);
        }
    };

    const int NKT = D / GM_KT;
    load_stage(0, 0);
    cp_commit();

    for (int kt = 0; kt < NKT; kt++) {
        if (kt + 1 < NKT) {
            load_stage((kt + 1) & 1, (kt + 1) * GM_KT);
            cp_commit();
            asm volatile("cp.async.wait_group 1;");
        } else {
            asm volatile("cp.async.wait_group 0;");
        }
        __syncthreads();

        const float* Ab = As + (kt & 1) * A_STAGE;
        const float* Wb = Ws + (kt & 1) * W_STAGE;

#pragma unroll
        for (int k16 = 0; k16 < GM_KT; k16 += 16) {
            const int c0k = k16 + 2 * tg;
            uint32_t ahi[2][4], alo[2][4];
#pragma unroll
            for (int mi = 0; mi < 2; mi++) {
                int ra = warp_m + mi * 16 + g;
                int rb = ra + 8;
                float av[8];
                av[0] = Ab[ra * AST + c0k];     av[1] = Ab[ra * AST + c0k + 1];
                av[2] = Ab[rb * AST + c0k];     av[3] = Ab[rb * AST + c0k + 1];
                av[4] = Ab[ra * AST + c0k + 8]; av[5] = Ab[ra * AST + c0k + 9];
                av[6] = Ab[rb * AST + c0k + 8]; av[7] = Ab[rb * AST + c0k + 9];
                uint16_t h[8], l[8];
#pragma unroll
                for (int j = 0; j < 8; j++) f2h_split(av[j], h[j], l[j]);
#pragma unroll
                for (int j = 0; j < 4; j++) {
                    ahi[mi][j] = packh2(h[2 * j], h[2 * j + 1]);
                    alo[mi][j] = packh2(l[2 * j], l[2 * j + 1]);
                }
            }
            uint32_t bhi[4][2], blo[4][2];
#pragma unroll
            for (int ni = 0; ni < 4; ni++) {
                int n0 = warp_n + ni * 8 + g;
                float bv[4];
                bv[0] = Wb[(c0k)     * WST + n0]; bv[1] = Wb[(c0k + 1) * WST + n0];
                bv[2] = Wb[(c0k + 8) * WST + n0]; bv[3] = Wb[(c0k + 9) * WST + n0];
                uint16_t h[4], l[4];
#pragma unroll
                for (int j = 0; j < 4; j++) f2h_split(bv[j], h[j], l[j]);
                bhi[ni][0] = packh2(h[0], h[1]); bhi[ni][1] = packh2(h[2], h[3]);
                blo[ni][0] = packh2(l[0], l[1]); blo[ni][1] = packh2(l[2], l[3]);
            }
#pragma unroll
            for (int mi = 0; mi < 2; mi++)
#pragma unroll
                for (int ni = 0; ni < 4; ni++) {
                    mma_f16(c[mi][ni], alo[mi], bhi[ni]);
                    mma_f16(c[mi][ni], ahi[mi], blo[ni]);
                    mma_f16(c[mi][ni], ahi[mi], bhi[ni]);
                }
        }
        __syncthreads();
    }

#pragma unroll
    for (int mi = 0; mi < 2; mi++)
#pragma unroll
        for (int ni = 0; ni < 4; ni++) {
            int row = brow + warp_m + mi * 16 + g;
            int col = bcol + warp_n + ni * 8 + 2 * tg;
            float2 v0 = make_float2(c[mi][ni][0], c[mi][ni][1]);
            float2 v1 = make_float2(c[mi][ni][2], c[mi][ni][3]);
            *reinterpret_cast<float2*>(&g_cw[(size_t)row * D + col]) = v0;
            *reinterpret_cast<float2*>(&g_cw[(size_t)(row + 8) * D + col]) = v1;
        }
}

// Dynamic SMEM layout for fuse kernel (floats). EXACTLY 56 KB so 4 CTAs fit
// under the 8 KB smem allocation granularity (4 x 56 = 224 <= 228 KB).
// The cp.async z-ring (DEPTH pairs) aliases the epilogue buffers AND the
// SS/R0/R1 scalars (all used only after wait_group 0 + __syncthreads).
#define OFF_CW0  0
#define OFF_CW1  (OFF_CW0 + D)
#define OFF_C0   (OFF_CW1 + D)
#define OFF_C1   (OFF_C0 + D)
#define OFF_RING (OFF_C1 + D)                    // NW*DEPTH*2*D floats
#define RING_FLOATS (NW * DEPTH * 2 * D)         // 12288
#define OFF_BUFC OFF_RING                        // aliased: NW*D
#define OFF_BA0  (OFF_BUFC + NW * D)
#define OFF_BA1  (OFF_BA0 + NW * D)
#define OFF_SS   (OFF_BA1 + NW * D)              // aliased into ring tail
#define OFF_R0   (OFF_SS + NW)
#define OFF_R1   (OFF_R0 + NW)
#define SMEM_FLOATS (OFF_RING + RING_FLOATS)     // 14336 -> 57344 B = 56 KB
#define SMEM_BYTES  (SMEM_FLOATS * 4)

// ---------------------------------------------------------------------------
// Kernel 2: one CTA (4 warps, 128 thr, <=128 regs, 4 CTAs/SM) per sample.
// Row-pair processing; per-warp cp.async ring of DEPTH=3 pairs (6 rows in
// flight) so compute and DRAM phases overlap instead of alternating.
// No atomics; branchless unshifted softmax.
// ---------------------------------------------------------------------------
__global__ __launch_bounds__(NT, 4) void fuse_kernel(
    const float* __restrict__ text,
    const float* __restrict__ img,
    const float* __restrict__ comment,
    const int*   __restrict__ comment_num,
    const float* __restrict__ W_ca,
    const float* __restrict__ W_co,
    float* __restrict__ out)
{
    extern __shared__ float sm[];
    const int b = blockIdx.x;
    const int tid = threadIdx.x;
    const int w = tid >> 5;
    const int lane = tid & 31;

    for (int d = tid; d < D; d += NT) {
        sm[OFF_CW0 + d] = g_cw[(size_t)(2 * b) * D + d];
        sm[OFF_CW1 + d] = g_cw[(size_t)(2 * b + 1) * D + d];
        sm[OFF_C0 + d]  = text[(size_t)b * D + d];
        sm[OFF_C1 + d]  = img[(size_t)b * D + d];
    }
    __syncthreads();

    const float LOG2E = 1.4426950408889634f;
    float4 wr[4];
#pragma unroll
    for (int j = 0; j < 4; j++) {
        float4 wv = __ldg(&reinterpret_cast<const float4*>(W_co)[lane + 32 * j]);
        wr[j] = make_float4(wv.x * LOG2E, wv.y * LOG2E, wv.z * LOG2E, wv.w * LOG2E);
    }

    const int num = comment_num[b];
    const float4* zbase = reinterpret_cast<const float4*>(comment + (size_t)b * N * D);

    float4 aA0[4], aA1[4], aC[4];
#pragma unroll
    for (int j = 0; j < 4; j++) {
        aA0[j] = make_float4(0.f, 0.f, 0.f, 0.f);
        aA1[j] = make_float4(0.f, 0.f, 0.f, 0.f);
        aC[j]  = make_float4(0.f, 0.f, 0.f, 0.f);
    }
    float ssum = 0.f;

    // Issue one pair (rows n0, n0+NW) into ring slot; ALWAYS commits exactly
    // one group so wait_group counting stays uniform.
    auto issue_pair = [&](int slot, int n0) {
        float* rb = sm + OFF_RING + (size_t)(w * (2 * DEPTH) + slot * 2) * D;
        if (n0 < num) {
            const float4* src = zbase + (size_t)n0 * (D / 4);
#pragma unroll
            for (int j = 0; j < 4; j++) {
                int q = lane + 32 * j;
                cp_async16(rb + q * 4, src + q);
            }
        }
        if (n0 + NW < num) {
            const float4* src = zbase + (size_t)(n0 + NW) * (D / 4);
#pragma unroll
            for (int j = 0; j < 4; j++) {
                int q = lane + 32 * j;
                cp_async16(rb + D + q * 4, src + q);
            }
        }
        cp_commit();
    };

    issue_pair(0, w);
    issue_pair(1, w + 2 * NW);
    issue_pair(2, w + 4 * NW);

    int p = 0;
    for (int n = w; n < num; n += 2 * NW) {
        asm volatile("cp.async.wait_group 2;");
        const bool hasB = (n + NW) < num;
        const float4* rb = reinterpret_cast<const float4*>(
            sm + OFF_RING + (size_t)(w * (2 * DEPTH) + p * 2) * D);

        float4 zcA[4], zcB[4];
#pragma unroll
        for (int j = 0; j < 4; j++) zcA[j] = rb[lane + 32 * j];
        if (hasB) {
#pragma unroll
            for (int j = 0; j < 4; j++) zcB[j] = rb[D / 4 + lane + 32 * j];
        } else {
#pragma unroll
            for (int j = 0; j < 4; j++) zcB[j] = make_float4(0.f, 0.f, 0.f, 0.f);
        }

        // refill this slot with the pair DEPTH ahead (commit unconditional)
        issue_pair(p, n + 2 * DEPTH * NW);
        if (++p == DEPTH) p = 0;

        // ---- dots with cw0/cw1 for BOTH rows (shared LDS) ----
        float dA0 = 0.f, dA1 = 0.f, dB0 = 0.f, dB1 = 0.f;
#pragma unroll
        for (int j = 0; j < 4; j++) {
            int q = lane + 32 * j;
            float4 a = reinterpret_cast<const float4*>(sm + OFF_CW0)[q];
            float4 c = reinterpret_cast<const float4*>(sm + OFF_CW1)[q];
            dA0 = fmaf(zcA[j].x, a.x, fmaf(zcA[j].y, a.y, fmaf(zcA[j].z, a.z, fmaf(zcA[j].w, a.w, dA0))));
            dA1 = fmaf(zcA[j].x, c.x, fmaf(zcA[j].y, c.y, fmaf(zcA[j].z, c.z, fmaf(zcA[j].w, c.w, dA1))));
            dB0 = fmaf(zcB[j].x, a.x, fmaf(zcB[j].y, a.y, fmaf(zcB[j].z, a.z, fmaf(zcB[j].w, a.w, dB0))));
            dB1 = fmaf(zcB[j].x, c.x, fmaf(zcB[j].y, c.y, fmaf(zcB[j].z, c.z, fmaf(zcB[j].w, c.w, dB1))));
        }
#pragma unroll
        for (int off = 16; off; off >>= 1) {
            dA0 += __shfl_xor_sync(0xffffffffu, dA0, off);
            dA1 += __shfl_xor_sync(0xffffffffu, dA1, off);
            dB0 += __shfl_xor_sync(0xffffffffu, dB0, off);
            dB1 += __shfl_xor_sync(0xffffffffu, dB1, off);
        }
        float t0A = tanha(dA0), t1A = tanha(dA1);
        float t0B = tanha(dB0), t1B = tanha(dB1);
        if (!hasB) { t0B = 0.f; t1B = 0.f; }

        // ---- logits + accA for both rows (c0/c1 LDS shared) ----
        float lpA = 0.f, lpB = 0.f;
#pragma unroll
        for (int j = 0; j < 4; j++) {
            int q = lane + 32 * j;
            float4 c0 = reinterpret_cast<const float4*>(sm + OFF_C0)[q];
            float4 c1 = reinterpret_cast<const float4*>(sm + OFF_C1)[q];
            float zt;
            zt = tanha(fmaf(t0A, c0.x, fmaf(t1A, c1.x, zcA[j].x))); lpA = fmaf(zt, wr[j].x, lpA);
            zt = tanha(fmaf(t0B, c0.x, fmaf(t1B, c1.x, zcB[j].x))); lpB = fmaf(zt, wr[j].x, lpB);
            zt = tanha(fmaf(t0A, c0.y, fmaf(t1A, c1.y, zcA[j].y))); lpA = fmaf(zt, wr[j].y, lpA);
            zt = tanha(fmaf(t0B, c0.y, fmaf(t1B, c1.y, zcB[j].y))); lpB = fmaf(zt, wr[j].y, lpB);
            zt = tanha(fmaf(t0A, c0.z, fmaf(t1A, c1.z, zcA[j].z))); lpA = fmaf(zt, wr[j].z, lpA);
            zt = tanha(fmaf(t0B, c0.z, fmaf(t1B, c1.z, zcB[j].z))); lpB = fmaf(zt, wr[j].z, lpB);
            zt = tanha(fmaf(t0A, c0.w, fmaf(t1A, c1.w, zcA[j].w))); lpA = fmaf(zt, wr[j].w, lpA);
            zt = tanha(fmaf(t0B, c0.w, fmaf(t1B, c1.w, zcB[j].w))); lpB = fmaf(zt, wr[j].w, lpB);

            aA0[j].x = fmaf(t0A, zcA[j].x, fmaf(t0B, zcB[j].x, aA0[j].x));
            aA0[j].y = fmaf(t0A, zcA[j].y, fmaf(t0B, zcB[j].y, aA0[j].y));
            aA0[j].z = fmaf(t0A, zcA[j].z, fmaf(t0B, zcB[j].z, aA0[j].z));
            aA0[j].w = fmaf(t0A, zcA[j].w, fmaf(t0B, zcB[j].w, aA0[j].w));
            aA1[j].x = fmaf(t1A, zcA[j].x, fmaf(t1B, zcB[j].x, aA1[j].x));
            aA1[j].y = fmaf(t1A, zcA[j].y, fmaf(t1B, zcB[j].y, aA1[j].y));
            aA1[j].z = fmaf(t1A, zcA[j].z, fmaf(t1B, zcB[j].z, aA1[j].z));
            aA1[j].w = fmaf(t1A, zcA[j].w, fmaf(t1B, zcB[j].w, aA1[j].w));
        }
#pragma unroll
        for (int off = 16; off; off >>= 1) {
            lpA += __shfl_xor_sync(0xffffffffu, lpA, off);
            lpB += __shfl_xor_sync(0xffffffffu, lpB, off);
        }
        float eA = ex2(lpA);
        float eB = hasB ? ex2(lpB) : 0.f;
        ssum += eA + eB;
#pragma unroll
        for (int j = 0; j < 4; j++) {
            aC[j].x = fmaf(eA, zcA[j].x, fmaf(eB, zcB[j].x, aC[j].x));
            aC[j].y = fmaf(eA, zcA[j].y, fmaf(eB, zcB[j].y, aC[j].y));
            aC[j].z = fmaf(eA, zcA[j].z, fmaf(eB, zcB[j].z, aC[j].z));
            aC[j].w = fmaf(eA, zcA[j].w, fmaf(eB, zcB[j].w, aC[j].w));
        }
    }

    // Drain all ring traffic before the region is reused (epilogue buffers
    // and SS/R0/R1 all alias the ring).
    asm volatile("cp.async.wait_group 0;");
    __syncthreads();

    if (lane == 0) sm[OFF_SS + w] = ssum;
#pragma unroll
    for (int j = 0; j < 4; j++) {
        int q = lane + 32 * j;
        reinterpret_cast<float4*>(sm + OFF_BUFC + w * D)[q] = aC[j];
        reinterpret_cast<float4*>(sm + OFF_BA0 + w * D)[q]  = aA0[j];
        reinterpret_cast<float4*>(sm + OFF_BA1 + w * D)[q]  = aA1[j];
    }
    __syncthreads();

    float S = 0.f;
#pragma unroll
    for (int i = 0; i < NW; i++) S += sm[OFF_SS + i];
    float invS = __frcp_rn(S);

    float p0 = 0.f, p1 = 0.f;
    for (int d = tid; d < D; d += NT) {
        float rc = 0.f, a0 = 0.f, a1 = 0.f;
#pragma unroll
        for (int i = 0; i < NW; i++) {
            rc += sm[OFF_BUFC + i * D + d];
            a0 += sm[OFF_BA0 + i * D + d];
            a1 += sm[OFF_BA1 + i * D + d];
        }
        out[BD + (size_t)b * D + d] = rc * invS;
        float wca = __ldg(&W_ca[d]);
        p0 = fmaf(tanha(sm[OFF_C0 + d] + a0), wca, p0);
        p1 = fmaf(tanha(sm[OFF_C1 + d] + a1), wca, p1);
    }
#pragma unroll
    for (int off = 16; off; off >>= 1) {
        p0 += __shfl_xor_sync(0xffffffffu, p0, off);
        p1 += __shfl_xor_sync(0xffffffffu, p1, off);
    }
    if (lane == 0) { sm[OFF_R0 + w] = p0; sm[OFF_R1 + w] = p1; }
    __syncthreads();

    float L0 = 0.f, L1 = 0.f;
#pragma unroll
    for (int i = 0; i < NW; i++) { L0 += sm[OFF_R0 + i]; L1 += sm[OFF_R1 + i]; }
    float mm = fmaxf(L0, L1);
    float e0 = __expf(L0 - mm), e1 = __expf(L1 - mm);
    float inv2 = __frcp_rn(e0 + e1);
    float w0 = e0 * inv2, w1 = e1 * inv2;
    if (tid == 0) {
        out[2 * BD + 2 * b + 0] = w0;
        out[2 * BD + 2 * b + 1] = w1;
    }
    for (int d = tid; d < D; d += NT)
        out[(size_t)b * D + d] = fmaf(sm[OFF_C0 + d], w0, sm[OFF_C1 + d] * w1);
}

extern "C" void kernel_launch(void* const* d_in, const int* in_sizes, int n_in,
                              void* d_out, int out_size)
{
    const float* text        = (const float*)d_in[0];
    const float* img         = (const float*)d_in[1];
    const float* comment     = (const float*)d_in[2];
    const int*   comment_num = (const int*)d_in[3];
    const float* cow         = (const float*)d_in[4];
    const float* W_ca        = (const float*)d_in[5];
    // d_in[6] = b_ca: cancels in softmax
    const float* W_co        = (const float*)d_in[7];
    // d_in[8] = b_co: cancels in softmax
    float* out = (float*)d_out;

    cudaFuncSetAttribute(gemm_cw_f16, cudaFuncAttributeMaxDynamicSharedMemorySize, GEMM_SMEM_BYTES);
    cudaFuncSetAttribute(fuse_kernel, cudaFuncAttributeMaxDynamicSharedMemorySize, SMEM_BYTES);

    dim3 g1(D / 128, (2 * B) / 64);   // (4, 64) = 256 CTAs
    gemm_cw_f16<<<g1, 256, GEMM_SMEM_BYTES>>>(text, img, cow);
    fuse_kernel<<<B, NT, SMEM_BYTES>>>(text, img, comment, comment_num, W_ca, W_co, out);
}

// round 17
// speedup vs baseline: 1.2242x; 1.2242x over previous
#include <cuda_runtime.h>
#include <cuda_fp16.h>
#include <math.h>
#include <stdint.h>

#define B 2048
#define N 128
#define D 512
#define BD (B * D)
#define NW 4             // warps per CTA in fuse kernel
#define NT (NW * 32)     // 128 threads

// Scratch: cw = content @ cow (rows interleaved: 2b=text[b], 2b+1=img[b])
__device__ float g_cw[2 * B * D];

// Pre-split fp16 operands for the GEMM.
// A: [4096][512] k-contiguous (row 2b=text[b], 2b+1=img[b]).
// W: TRANSPOSED [n][k] so k-adjacent pairs pack into one 32-bit word.
__device__ __half g_ahi[2 * B * D];
__device__ __half g_alo[2 * B * D];
__device__ __half g_whi[D * D];
__device__ __half g_wlo[D * D];

__device__ __forceinline__ float tanha(float x) {
    float y;
    asm("tanh.approx.f32 %0, %1;" : "=f"(y) : "f"(x));
    return y;
}
__device__ __forceinline__ float ex2(float x) {
    float y;
    asm("ex2.approx.f32 %0, %1;" : "=f"(y) : "f"(x));
    return y;
}
__device__ __forceinline__ void cp_async16(void* smem_dst, const void* gmem_src) {
    uint32_t s = (uint32_t)__cvta_generic_to_shared(smem_dst);
    asm volatile("cp.async.ca.shared.global [%0], [%1], 16;" :: "r"(s), "l"(gmem_src));
}
__device__ __forceinline__ void cp_commit() {
    asm volatile("cp.async.commit_group;");
}
__device__ __forceinline__ void f2h_split(float x, __half& hi, __half& lo) {
    hi = __float2half_rn(x);
    lo = __float2half_rn(x - __half2float(hi));
}

// m16n8k16 row.col f32.f16.f16.f32
__device__ __forceinline__ void mma_f16(float c[4], const uint32_t a[4], const uint32_t b[2]) {
    asm volatile(
        "mma.sync.aligned.m16n8k16.row.col.f32.f16.f16.f32 "
        "{%0,%1,%2,%3}, {%4,%5,%6,%7}, {%8,%9}, {%0,%1,%2,%3};"
        : "+f"(c[0]), "+f"(c[1]), "+f"(c[2]), "+f"(c[3])
        : "r"(a[0]), "r"(a[1]), "r"(a[2]), "r"(a[3]), "r"(b[0]), "r"(b[1]));
}

// ---------------------------------------------------------------------------
// Prep A: split fp32 content rows into fp16 hi/lo, k-contiguous.
// ---------------------------------------------------------------------------
__global__ __launch_bounds__(128) void prep_a(
    const float* __restrict__ text, const float* __restrict__ img)
{
    const int r = blockIdx.x;            // 0..4095
    const int k = threadIdx.x * 4;       // 0..508
    const float* src = ((r & 1) ? img : text) + (size_t)(r >> 1) * D + k;
    float4 v = *reinterpret_cast<const float4*>(src);
    __half h[4], l[4];
    f2h_split(v.x, h[0], l[0]);
    f2h_split(v.y, h[1], l[1]);
    f2h_split(v.z, h[2], l[2]);
    f2h_split(v.w, h[3], l[3]);
    *reinterpret_cast<uint2*>(&g_ahi[(size_t)r * D + k]) = *reinterpret_cast<uint2*>(h);
    *reinterpret_cast<uint2*>(&g_alo[(size_t)r * D + k]) = *reinterpret_cast<uint2*>(l);
}

// ---------------------------------------------------------------------------
// Prep W: transpose cow[k][n] -> Wt[n][k] with fp16 hi/lo split (SMEM-staged).
// ---------------------------------------------------------------------------
__global__ __launch_bounds__(256) void prep_w(const float* __restrict__ cow)
{
    __shared__ float tile[32][33];
    const int bx = blockIdx.x & 15, by = blockIdx.x >> 4;
    const int tx = threadIdx.x & 31, ty = threadIdx.x >> 5;   // 32x8
#pragma unroll
    for (int i = 0; i < 4; i++) {
        int k = by * 32 + ty + i * 8;
        int n = bx * 32 + tx;
        tile[ty + i * 8][tx] = cow[(size_t)k * D + n];
    }
    __syncthreads();
#pragma unroll
    for (int i = 0; i < 4; i++) {
        int n = bx * 32 + ty + i * 8;
        int k = by * 32 + tx;
        float x = tile[tx][ty + i * 8];
        __half h, l;
        f2h_split(x, h, l);
        g_whi[(size_t)n * D + k] = h;
        g_wlo[(size_t)n * D + k] = l;
    }
}

// ---------------------------------------------------------------------------
// Kernel 1: cw[4096,512] = A @ cow via fp16x3 mma.sync, operands pre-split.
// Tile M=64 N=128 K=32; grid 256 CTAs; 2-stage cp.async double buffering.
// All fragment registers are single conflict-free LDS.32 of packed pairs
// (20-word row strides: 20*row+tg covers all 32 banks over 8 rows x 4 tg).
// ---------------------------------------------------------------------------
#define GM_KT 32
#define ASTW 20                  // A row stride (32-bit words): 16 data + 4 pad
#define WSTW 20                  // Wt row stride (words)
#define A_WORDS (64 * ASTW)      // 1280
#define W_WORDS (128 * WSTW)     // 2560
#define AOFF_LO A_WORDS
#define WOFF_HI (2 * A_WORDS)
#define WOFF_LO (2 * A_WORDS + W_WORDS)
#define STAGE_WORDS (2 * A_WORDS + 2 * W_WORDS)   // 7680
#define GEMM_SMEM_BYTES (2 * STAGE_WORDS * 4)     // 61440

__global__ __launch_bounds__(256) void gemm_cw_f16(void)
{
    extern __shared__ uint32_t gw[];

    const int t = threadIdx.x;
    const int wid = t >> 5;
    const int lane = t & 31;
    const int warp_m = (wid & 1) * 32;
    const int warp_n = (wid >> 1) * 32;
    const int brow = blockIdx.y * 64;
    const int bcol = blockIdx.x * 128;
    const int g  = lane >> 2;   // 0..7
    const int tg = lane & 3;    // 0..3

    float c[2][4][4];
#pragma unroll
    for (int mi = 0; mi < 2; mi++)
#pragma unroll
        for (int ni = 0; ni < 4; ni++)
#pragma unroll
            for (int j = 0; j < 4; j++) c[mi][ni][j] = 0.f;

    // Stage loader: A rows 64 x 32 fp16 (64B each), W rows 128 x 32 fp16.
    auto load_stage = [&](int st, int k0) {
        uint32_t* base = gw + st * STAGE_WORDS;
        {   // A: 256 chunks per array, 1 per thread
            int r = t >> 2, cch = t & 3;
            cp_async16(base + r * ASTW + cch * 4,
                       g_ahi + (size_t)(brow + r) * D + k0 + cch * 8);
            cp_async16(base + AOFF_LO + r * ASTW + cch * 4,
                       g_alo + (size_t)(brow + r) * D + k0 + cch * 8);
        }
#pragma unroll
        for (int s = 0; s < 2; s++) {   // W: 512 chunks per array, 2 per thread
            int f = t + 256 * s;
            int n = f >> 2, cch = f & 3;
            cp_async16(base + WOFF_HI + n * WSTW + cch * 4,
                       g_whi + (size_t)(bcol + n) * D + k0 + cch * 8);
            cp_async16(base + WOFF_LO + n * WSTW + cch * 4,
                       g_wlo + (size_t)(bcol + n) * D + k0 + cch * 8);
        }
        cp_commit();
    };

    const int NKT = D / GM_KT;   // 16
    load_stage(0, 0);

    for (int kt = 0; kt < NKT; kt++) {
        if (kt + 1 < NKT) {
            load_stage((kt + 1) & 1, (kt + 1) * GM_KT);
            asm volatile("cp.async.wait_group 1;");
        } else {
            asm volatile("cp.async.wait_group 0;");
        }
        __syncthreads();

        const uint32_t* Ah = gw + (kt & 1) * STAGE_WORDS;
        const uint32_t* Al = Ah + AOFF_LO;
        const uint32_t* Wh = gw + (kt & 1) * STAGE_WORDS + WOFF_HI;
        const uint32_t* Wl = gw + (kt & 1) * STAGE_WORDS + WOFF_LO;

#pragma unroll
        for (int k16 = 0; k16 < GM_KT; k16 += 16) {
            const int kw = (k16 >> 1) + tg;   // word index of packed pair
            uint32_t ahi[2][4], alo[2][4];
#pragma unroll
            for (int mi = 0; mi < 2; mi++) {
                int ra = warp_m + mi * 16 + g;
                int rb = ra + 8;
                ahi[mi][0] = Ah[ra * ASTW + kw];
                ahi[mi][1] = Ah[rb * ASTW + kw];
                ahi[mi][2] = Ah[ra * ASTW + kw + 4];
                ahi[mi][3] = Ah[rb * ASTW + kw + 4];
                alo[mi][0] = Al[ra * ASTW + kw];
                alo[mi][1] = Al[rb * ASTW + kw];
                alo[mi][2] = Al[ra * ASTW + kw + 4];
                alo[mi][3] = Al[rb * ASTW + kw + 4];
            }
            uint32_t bhi[4][2], blo[4][2];
#pragma unroll
            for (int ni = 0; ni < 4; ni++) {
                int n0 = warp_n + ni * 8 + g;
                bhi[ni][0] = Wh[n0 * WSTW + kw];
                bhi[ni][1] = Wh[n0 * WSTW + kw + 4];
                blo[ni][0] = Wl[n0 * WSTW + kw];
                blo[ni][1] = Wl[n0 * WSTW + kw + 4];
            }
#pragma unroll
            for (int mi = 0; mi < 2; mi++)
#pragma unroll
                for (int ni = 0; ni < 4; ni++) {
                    mma_f16(c[mi][ni], alo[mi], bhi[ni]);
                    mma_f16(c[mi][ni], ahi[mi], blo[ni]);
                    mma_f16(c[mi][ni], ahi[mi], bhi[ni]);
                }
        }
        __syncthreads();
    }

    // Store C: c[mi][ni] = {(row g, col 2tg), (g, 2tg+1), (g+8, 2tg), (g+8, 2tg+1)}
#pragma unroll
    for (int mi = 0; mi < 2; mi++)
#pragma unroll
        for (int ni = 0; ni < 4; ni++) {
            int row = brow + warp_m + mi * 16 + g;
            int col = bcol + warp_n + ni * 8 + 2 * tg;
            float2 v0 = make_float2(c[mi][ni][0], c[mi][ni][1]);
            float2 v1 = make_float2(c[mi][ni][2], c[mi][ni][3]);
            *reinterpret_cast<float2*>(&g_cw[(size_t)row * D + col]) = v0;
            *reinterpret_cast<float2*>(&g_cw[(size_t)(row + 8) * D + col]) = v1;
        }
}

// Dynamic SMEM layout for fuse kernel (floats) — R13 layout (depth-2 ring,
// ring aliases epilogue buffers; guarded by wait_group 0 + __syncthreads).
#define OFF_CW0  0
#define OFF_CW1  (OFF_CW0 + D)
#define OFF_C0   (OFF_CW1 + D)
#define OFF_C1   (OFF_C0 + D)
#define OFF_RING (OFF_C1 + D)
#define RING_FLOATS (NW * 2 * 2 * D)
#define OFF_BUFC OFF_RING
#define OFF_BA0  (OFF_BUFC + NW * D)
#define OFF_BA1  (OFF_BA0 + NW * D)
#define OFF_SS   (OFF_RING + RING_FLOATS)
#define OFF_R0   (OFF_SS + NW)
#define OFF_R1   (OFF_R0 + NW)
#define SMEM_FLOATS (OFF_R1 + NW)
#define SMEM_BYTES  (SMEM_FLOATS * 4)

// ---------------------------------------------------------------------------
// Kernel 2: fuse — R13 version verbatim (75.1 us; best measured).
// ---------------------------------------------------------------------------
__global__ __launch_bounds__(NT, 4) void fuse_kernel(
    const float* __restrict__ text,
    const float* __restrict__ img,
    const float* __restrict__ comment,
    const int*   __restrict__ comment_num,
    const float* __restrict__ W_ca,
    const float* __restrict__ W_co,
    float* __restrict__ out)
{
    extern __shared__ float sm[];
    const int b = blockIdx.x;
    const int tid = threadIdx.x;
    const int w = tid >> 5;
    const int lane = tid & 31;

    for (int d = tid; d < D; d += NT) {
        sm[OFF_CW0 + d] = g_cw[(size_t)(2 * b) * D + d];
        sm[OFF_CW1 + d] = g_cw[(size_t)(2 * b + 1) * D + d];
        sm[OFF_C0 + d]  = text[(size_t)b * D + d];
        sm[OFF_C1 + d]  = img[(size_t)b * D + d];
    }
    __syncthreads();

    const float LOG2E = 1.4426950408889634f;
    float4 wr[4];
#pragma unroll
    for (int j = 0; j < 4; j++) {
        float4 wv = __ldg(&reinterpret_cast<const float4*>(W_co)[lane + 32 * j]);
        wr[j] = make_float4(wv.x * LOG2E, wv.y * LOG2E, wv.z * LOG2E, wv.w * LOG2E);
    }

    const int num = comment_num[b];
    const float4* zbase = reinterpret_cast<const float4*>(comment + (size_t)b * N * D);

    float4 aA0[4], aA1[4], aC[4];
#pragma unroll
    for (int j = 0; j < 4; j++) {
        aA0[j] = make_float4(0.f, 0.f, 0.f, 0.f);
        aA1[j] = make_float4(0.f, 0.f, 0.f, 0.f);
        aC[j]  = make_float4(0.f, 0.f, 0.f, 0.f);
    }
    float ssum = 0.f;

    auto issue_pair = [&](int slot, int n0) {
        float* rb = sm + OFF_RING + (size_t)(w * 4 + slot * 2) * D;
        if (n0 < num) {
            const float4* src = zbase + (size_t)n0 * (D / 4);
#pragma unroll
            for (int j = 0; j < 4; j++) {
                int q = lane + 32 * j;
                cp_async16(rb + q * 4, src + q);
            }
        }
        if (n0 + NW < num) {
            const float4* src = zbase + (size_t)(n0 + NW) * (D / 4);
#pragma unroll
            for (int j = 0; j < 4; j++) {
                int q = lane + 32 * j;
                cp_async16(rb + D + q * 4, src + q);
            }
        }
        cp_commit();
    };

    issue_pair(0, w);
    issue_pair(1, w + 2 * NW);

    int p = 0;
    for (int n = w; n < num; n += 2 * NW, p ^= 1) {
        asm volatile("cp.async.wait_group 1;");
        const bool hasB = (n + NW) < num;
        const float4* rb = reinterpret_cast<const float4*>(sm + OFF_RING + (size_t)(w * 4 + p * 2) * D);

        float4 zcA[4], zcB[4];
#pragma unroll
        for (int j = 0; j < 4; j++) zcA[j] = rb[lane + 32 * j];
        if (hasB) {
#pragma unroll
            for (int j = 0; j < 4; j++) zcB[j] = rb[D / 4 + lane + 32 * j];
        } else {
#pragma unroll
            for (int j = 0; j < 4; j++) zcB[j] = make_float4(0.f, 0.f, 0.f, 0.f);
        }

        issue_pair(p, n + 4 * NW);

        float dA0 = 0.f, dA1 = 0.f, dB0 = 0.f, dB1 = 0.f;
#pragma unroll
        for (int j = 0; j < 4; j++) {
            int q = lane + 32 * j;
            float4 a = reinterpret_cast<const float4*>(sm + OFF_CW0)[q];
            float4 c = reinterpret_cast<const float4*>(sm + OFF_CW1)[q];
            dA0 = fmaf(zcA[j].x, a.x, fmaf(zcA[j].y, a.y, fmaf(zcA[j].z, a.z, fmaf(zcA[j].w, a.w, dA0))));
            dA1 = fmaf(zcA[j].x, c.x, fmaf(zcA[j].y, c.y, fmaf(zcA[j].z, c.z, fmaf(zcA[j].w, c.w, dA1))));
            dB0 = fmaf(zcB[j].x, a.x, fmaf(zcB[j].y, a.y, fmaf(zcB[j].z, a.z, fmaf(zcB[j].w, a.w, dB0))));
            dB1 = fmaf(zcB[j].x, c.x, fmaf(zcB[j].y, c.y, fmaf(zcB[j].z, c.z, fmaf(zcB[j].w, c.w, dB1))));
        }
#pragma unroll
        for (int off = 16; off; off >>= 1) {
            dA0 += __shfl_xor_sync(0xffffffffu, dA0, off);
            dA1 += __shfl_xor_sync(0xffffffffu, dA1, off);
            dB0 += __shfl_xor_sync(0xffffffffu, dB0, off);
            dB1 += __shfl_xor_sync(0xffffffffu, dB1, off);
        }
        float t0A = tanha(dA0), t1A = tanha(dA1);
        float t0B = tanha(dB0), t1B = tanha(dB1);
        if (!hasB) { t0B = 0.f; t1B = 0.f; }

        float lpA = 0.f, lpB = 0.f;
#pragma unroll
        for (int j = 0; j < 4; j++) {
            int q = lane + 32 * j;
            float4 c0 = reinterpret_cast<const float4*>(sm + OFF_C0)[q];
            float4 c1 = reinterpret_cast<const float4*>(sm + OFF_C1)[q];
            float zt;
            zt = tanha(fmaf(t0A, c0.x, fmaf(t1A, c1.x, zcA[j].x))); lpA = fmaf(zt, wr[j].x, lpA);
            zt = tanha(fmaf(t0B, c0.x, fmaf(t1B, c1.x, zcB[j].x))); lpB = fmaf(zt, wr[j].x, lpB);
            zt = tanha(fmaf(t0A, c0.y, fmaf(t1A, c1.y, zcA[j].y))); lpA = fmaf(zt, wr[j].y, lpA);
            zt = tanha(fmaf(t0B, c0.y, fmaf(t1B, c1.y, zcB[j].y))); lpB = fmaf(zt, wr[j].y, lpB);
            zt = tanha(fmaf(t0A, c0.z, fmaf(t1A, c1.z, zcA[j].z))); lpA = fmaf(zt, wr[j].z, lpA);
            zt = tanha(fmaf(t0B, c0.z, fmaf(t1B, c1.z, zcB[j].z))); lpB = fmaf(zt, wr[j].z, lpB);
            zt = tanha(fmaf(t0A, c0.w, fmaf(t1A, c1.w, zcA[j].w))); lpA = fmaf(zt, wr[j].w, lpA);
            zt = tanha(fmaf(t0B, c0.w, fmaf(t1B, c1.w, zcB[j].w))); lpB = fmaf(zt, wr[j].w, lpB);

            aA0[j].x = fmaf(t0A, zcA[j].x, fmaf(t0B, zcB[j].x, aA0[j].x));
            aA0[j].y = fmaf(t0A, zcA[j].y, fmaf(t0B, zcB[j].y, aA0[j].y));
            aA0[j].z = fmaf(t0A, zcA[j].z, fmaf(t0B, zcB[j].z, aA0[j].z));
            aA0[j].w = fmaf(t0A, zcA[j].w, fmaf(t0B, zcB[j].w, aA0[j].w));
            aA1[j].x = fmaf(t1A, zcA[j].x, fmaf(t1B, zcB[j].x, aA1[j].x));
            aA1[j].y = fmaf(t1A, zcA[j].y, fmaf(t1B, zcB[j].y, aA1[j].y));
            aA1[j].z = fmaf(t1A, zcA[j].z, fmaf(t1B, zcB[j].z, aA1[j].z));
            aA1[j].w = fmaf(t1A, zcA[j].w, fmaf(t1B, zcB[j].w, aA1[j].w));
        }
#pragma unroll
        for (int off = 16; off; off >>= 1) {
            lpA += __shfl_xor_sync(0xffffffffu, lpA, off);
            lpB += __shfl_xor_sync(0xffffffffu, lpB, off);
        }
        float eA = ex2(lpA);
        float eB = hasB ? ex2(lpB) : 0.f;
        ssum += eA + eB;
#pragma unroll
        for (int j = 0; j < 4; j++) {
            aC[j].x = fmaf(eA, zcA[j].x, fmaf(eB, zcB[j].x, aC[j].x));
            aC[j].y = fmaf(eA, zcA[j].y, fmaf(eB, zcB[j].y, aC[j].y));
            aC[j].z = fmaf(eA, zcA[j].z, fmaf(eB, zcB[j].z, aC[j].z));
            aC[j].w = fmaf(eA, zcA[j].w, fmaf(eB, zcB[j].w, aC[j].w));
        }
    }

    asm volatile("cp.async.wait_group 0;");
    __syncthreads();

    if (lane == 0) sm[OFF_SS + w] = ssum;
#pragma unroll
    for (int j = 0; j < 4; j++) {
        int q = lane + 32 * j;
        reinterpret_cast<float4*>(sm + OFF_BUFC + w * D)[q] = aC[j];
        reinterpret_cast<float4*>(sm + OFF_BA0 + w * D)[q]  = aA0[j];
        reinterpret_cast<float4*>(sm + OFF_BA1 + w * D)[q]  = aA1[j];
    }
    __syncthreads();

    float S = 0.f;
#pragma unroll
    for (int i = 0; i < NW; i++) S += sm[OFF_SS + i];
    float invS = __frcp_rn(S);

    float p0 = 0.f, p1 = 0.f;
    for (int d = tid; d < D; d += NT) {
        float rc = 0.f, a0 = 0.f, a1 = 0.f;
#pragma unroll
        for (int i = 0; i < NW; i++) {
            rc += sm[OFF_BUFC + i * D + d];
            a0 += sm[OFF_BA0 + i * D + d];
            a1 += sm[OFF_BA1 + i * D + d];
        }
        out[BD + (size_t)b * D + d] = rc * invS;
        float wca = __ldg(&W_ca[d]);
        p0 = fmaf(tanha(sm[OFF_C0 + d] + a0), wca, p0);
        p1 = fmaf(tanha(sm[OFF_C1 + d] + a1), wca, p1);
    }
#pragma unroll
    for (int off = 16; off; off >>= 1) {
        p0 += __shfl_xor_sync(0xffffffffu, p0, off);
        p1 += __shfl_xor_sync(0xffffffffu, p1, off);
    }
    if (lane == 0) { sm[OFF_R0 + w] = p0; sm[OFF_R1 + w] = p1; }
    __syncthreads();

    float L0 = 0.f, L1 = 0.f;
#pragma unroll
    for (int i = 0; i < NW; i++) { L0 += sm[OFF_R0 + i]; L1 += sm[OFF_R1 + i]; }
    float mm = fmaxf(L0, L1);
    float e0 = __expf(L0 - mm), e1 = __expf(L1 - mm);
    float inv2 = __frcp_rn(e0 + e1);
    float w0 = e0 * inv2, w1 = e1 * inv2;
    if (tid == 0) {
        out[2 * BD + 2 * b + 0] = w0;
        out[2 * BD + 2 * b + 1] = w1;
    }
    for (int d = tid; d < D; d += NT)
        out[(size_t)b * D + d] = fmaf(sm[OFF_C0 + d], w0, sm[OFF_C1 + d] * w1);
}

extern "C" void kernel_launch(void* const* d_in, const int* in_sizes, int n_in,
                              void* d_out, int out_size)
{
    const float* text        = (const float*)d_in[0];
    const float* img         = (const float*)d_in[1];
    const float* comment     = (const float*)d_in[2];
    const int*   comment_num = (const int*)d_in[3];
    const float* cow         = (const float*)d_in[4];
    const float* W_ca        = (const float*)d_in[5];
    // d_in[6] = b_ca: cancels in softmax
    const float* W_co        = (const float*)d_in[7];
    // d_in[8] = b_co: cancels in softmax
    float* out = (float*)d_out;

    cudaFuncSetAttribute(gemm_cw_f16, cudaFuncAttributeMaxDynamicSharedMemorySize, GEMM_SMEM_BYTES);
    cudaFuncSetAttribute(fuse_kernel, cudaFuncAttributeMaxDynamicSharedMemorySize, SMEM_BYTES);

    prep_a<<<2 * B, 128>>>(text, img);
    prep_w<<<256, 256>>>(cow);
    dim3 g1(D / 128, (2 * B) / 64);   // (4, 64) = 256 CTAs
    gemm_cw_f16<<<g1, 256, GEMM_SMEM_BYTES>>>();
    fuse_kernel<<<B, NT, SMEM_BYTES>>>(text, img, comment, comment_num, W_ca, W_co, out);
}